// round 8
// baseline (speedup 1.0000x reference)
#include <cuda_runtime.h>
#include <cuda_bf16.h>
#include <cuda_fp16.h>

// GAT layer: N=100000, E=1600000, F=128, H=64.
//   K1 gemm   : h0(fp16) = x @ fc_w^T via TF32 mma.sync; fused s_src/s_dst,
//               zeroes {hsum,deg} float2 and scan flags
//   K2 edge1  : 2 edges/thread; he=exp(leaky); ONE red.v2.f32 {he,1} per edge
//   K3 scan   : single-pass exclusive scan (decoupled lookback) -> start,
//               and packed per-node {hsum, cursor} (one 8B sector for scatter)
//   K4 scatter: 2 edges/thread; alpha=he/hsum; pair[pos]=(dst, adj*alpha)
//   K5 gather : per-node register accumulation over fp16 h0 (8-way MLP)

#define NN 100000
#define EE 1600000
#define FF 128
#define HH 64
#define LEAKY 0.05f
#define NBLK ((NN + 1023) / 1024)   // 98 scan blocks (1024 nodes each)

__device__ __half g_h0h[NN * HH];   // 12.8 MB (fp16 h0)
__device__ float  g_ssrc[NN];
__device__ float  g_sdst[NN];
__device__ float2 g_hd[NN + 4];     // {hsum, deg} accumulated by edge1
__device__ float  g_he[EE];         // 6.4 MB
__device__ int    g_start[NN + 4];
__device__ int    g_hc[2 * NN + 8]; // packed {hsum_bits, cursor} per node
__device__ int    g_flag[NBLK];     // 0=none 1=aggregate 2=inclusive
__device__ int    g_aggr[NBLK];
__device__ int    g_incl[NBLK];
__device__ int2   g_sd[EE];         // 12.8 MB compact (src,dst)
__device__ int2   g_pair[EE];       // 12.8 MB (dst, adj*alpha)

__device__ __forceinline__ unsigned f2tf32(float f) {
    unsigned r;
    asm("cvt.rna.tf32.f32 %0, %1;" : "=r"(r) : "f"(f));
    return r;
}

// ---------------------------------------------------------------------------
// K1: h0[N,64] = x[N,128] @ W^T via tf32 mma.m16n8k8.
// ---------------------------------------------------------------------------
__global__ __launch_bounds__(256) void k_gemm(const float* __restrict__ x,
                                              const float* __restrict__ w,
                                              const float* __restrict__ aw) {
    __shared__ float As[128][33];
    __shared__ float Bs[32][68];

    const int tid  = threadIdx.x;
    const int wrp  = tid >> 5;
    const int lane = tid & 31;
    const int g    = lane >> 2;
    const int tg   = lane & 3;
    const int m0   = blockIdx.x * 128;
    const int mw   = wrp * 16;

    if (blockIdx.x == 0 && tid < NBLK) g_flag[tid] = 0;

    float acc[8][4];
#pragma unroll
    for (int i = 0; i < 8; i++)
#pragma unroll
        for (int j = 0; j < 4; j++) acc[i][j] = 0.f;

    for (int kc = 0; kc < FF; kc += 32) {
        {
            int k4 = tid & 7;
            int rb = tid >> 3;
#pragma unroll
            for (int r = 0; r < 4; r++) {
                int m = rb + r * 32;
                int gm = m0 + m;
                float4 v = make_float4(0.f, 0.f, 0.f, 0.f);
                if (gm < NN) v = *(const float4*)&x[(long long)gm * FF + kc + k4 * 4];
                As[m][k4 * 4 + 0] = __uint_as_float(f2tf32(v.x));
                As[m][k4 * 4 + 1] = __uint_as_float(f2tf32(v.y));
                As[m][k4 * 4 + 2] = __uint_as_float(f2tf32(v.z));
                As[m][k4 * 4 + 3] = __uint_as_float(f2tf32(v.w));
            }
        }
        {
            int h = tid >> 2;
            int kq = tid & 3;
#pragma unroll
            for (int j = 0; j < 2; j++) {
                int kk = kq * 4 + j * 16;
                float4 v = *(const float4*)&w[h * FF + kc + kk];
                Bs[kk + 0][h] = __uint_as_float(f2tf32(v.x));
                Bs[kk + 1][h] = __uint_as_float(f2tf32(v.y));
                Bs[kk + 2][h] = __uint_as_float(f2tf32(v.z));
                Bs[kk + 3][h] = __uint_as_float(f2tf32(v.w));
            }
        }
        __syncthreads();
#pragma unroll
        for (int ks = 0; ks < 4; ks++) {
            int kk = ks * 8;
            unsigned a0 = __float_as_uint(As[mw + g][kk + tg]);
            unsigned a1 = __float_as_uint(As[mw + g + 8][kk + tg]);
            unsigned a2 = __float_as_uint(As[mw + g][kk + tg + 4]);
            unsigned a3 = __float_as_uint(As[mw + g + 8][kk + tg + 4]);
#pragma unroll
            for (int nt = 0; nt < 8; nt++) {
                int n0 = nt * 8;
                unsigned b0 = __float_as_uint(Bs[kk + tg][n0 + g]);
                unsigned b1 = __float_as_uint(Bs[kk + tg + 4][n0 + g]);
                asm volatile(
                    "mma.sync.aligned.m16n8k8.row.col.f32.tf32.tf32.f32 "
                    "{%0,%1,%2,%3}, {%4,%5,%6,%7}, {%8,%9}, {%0,%1,%2,%3};"
                    : "+f"(acc[nt][0]), "+f"(acc[nt][1]),
                      "+f"(acc[nt][2]), "+f"(acc[nt][3])
                    : "r"(a0), "r"(a1), "r"(a2), "r"(a3), "r"(b0), "r"(b1));
            }
        }
        __syncthreads();
    }

    int r0 = m0 + mw + g;
    int r1 = r0 + 8;
    float ps0 = 0.f, pd0 = 0.f, ps1 = 0.f, pd1 = 0.f;
#pragma unroll
    for (int nt = 0; nt < 8; nt++) {
        int c = nt * 8 + 2 * tg;
        float w0 = __ldg(&aw[c]), w1 = __ldg(&aw[c + 1]);
        float u0 = __ldg(&aw[64 + c]), u1 = __ldg(&aw[64 + c + 1]);
        ps0 += acc[nt][0] * w0 + acc[nt][1] * w1;
        pd0 += acc[nt][0] * u0 + acc[nt][1] * u1;
        ps1 += acc[nt][2] * w0 + acc[nt][3] * w1;
        pd1 += acc[nt][2] * u0 + acc[nt][3] * u1;
        if (r0 < NN)
            *(__half2*)&g_h0h[r0 * HH + c] = __floats2half2_rn(acc[nt][0], acc[nt][1]);
        if (r1 < NN)
            *(__half2*)&g_h0h[r1 * HH + c] = __floats2half2_rn(acc[nt][2], acc[nt][3]);
    }
#pragma unroll
    for (int o = 1; o < 4; o <<= 1) {
        ps0 += __shfl_down_sync(0xFFFFFFFFu, ps0, o, 4);
        pd0 += __shfl_down_sync(0xFFFFFFFFu, pd0, o, 4);
        ps1 += __shfl_down_sync(0xFFFFFFFFu, ps1, o, 4);
        pd1 += __shfl_down_sync(0xFFFFFFFFu, pd1, o, 4);
    }
    if (tg == 0) {
        if (r0 < NN) { g_ssrc[r0] = ps0; g_sdst[r0] = pd0; }
        if (r1 < NN) { g_ssrc[r1] = ps1; g_sdst[r1] = pd1; }
    }
    if (tid < 128) {
        int gm = m0 + tid;
        if (gm < NN) g_hd[gm] = make_float2(0.f, 0.f);
    }
}

// ---------------------------------------------------------------------------
// K2: 2 edges/thread; he=exp(leaky(logit)); one red.v2.f32 {he, 1} per edge.
// ---------------------------------------------------------------------------
__global__ __launch_bounds__(256) void k_edge1(const void* __restrict__ ei,
                                               const float* __restrict__ ab) {
    int lane = threadIdx.x & 31;
    const long long* p64 = (const long long*)ei;
    long long t0 = p64[lane], t1 = p64[lane + 32];
    bool ok = (t0 >= 0 && t0 < NN && t1 >= 0 && t1 < NN);
    bool is64 = (__ballot_sync(0xFFFFFFFFu, ok) == 0xFFFFFFFFu);

    int e = (blockIdx.x * blockDim.x + threadIdx.x) * 2;
    if (e >= EE) return;
    int s0, d0, s1, d1;
    if (is64) {
        longlong2 sp = *(const longlong2*)&p64[e];
        longlong2 dp = *(const longlong2*)&p64[EE + e];
        s0 = (int)sp.x; s1 = (int)sp.y;
        d0 = (int)dp.x; d1 = (int)dp.y;
    } else {
        const int* p32 = (const int*)ei;
        int2 sp = *(const int2*)&p32[e];
        int2 dp = *(const int2*)&p32[EE + e];
        s0 = sp.x; s1 = sp.y;
        d0 = dp.x; d1 = dp.y;
    }
    float bv = __ldg(&ab[0]);
    float v0 = g_ssrc[s0] + g_sdst[d0] + bv;
    float v1 = g_ssrc[s1] + g_sdst[d1] + bv;
    v0 = (v0 >= 0.f) ? v0 : LEAKY * v0;
    v1 = (v1 >= 0.f) ? v1 : LEAKY * v1;
    float h0 = expf(v0);
    float h1 = expf(v1);
    *(int4*)&g_sd[e] = make_int4(s0, d0, s1, d1);
    *(float2*)&g_he[e] = make_float2(h0, h1);
    asm volatile("red.global.add.v2.f32 [%0], {%1, %2};"
                 :: "l"(&g_hd[s0]), "f"(h0), "f"(1.0f) : "memory");
    asm volatile("red.global.add.v2.f32 [%0], {%1, %2};"
                 :: "l"(&g_hd[s1]), "f"(h1), "f"(1.0f) : "memory");
}

// ---------------------------------------------------------------------------
// K3: single-pass exclusive scan with decoupled lookback.
// Writes g_start (for gather) and packed g_hc = {hsum_bits, start} per node.
// ---------------------------------------------------------------------------
__global__ __launch_bounds__(256) void k_scan() {
    __shared__ int ws[8];
    __shared__ int sh_total, sh_off;
    const int b = blockIdx.x, t = threadIdx.x;
    const int lane = t & 31, wid = t >> 5;
    const int i0 = (b * 256 + t) * 4;

    int4 v = make_int4(0, 0, 0, 0);
    float4 hs = make_float4(0.f, 0.f, 0.f, 0.f);
    if (i0 < NN) {
        const float4* p = (const float4*)&g_hd[i0];
        float4 abv = p[0];
        float4 cdv = p[1];
        hs = make_float4(abv.x, abv.z, cdv.x, cdv.z);
        v.x = (int)abv.y;
        v.y = (i0 + 1 < NN) ? (int)abv.w : 0;
        v.z = (i0 + 2 < NN) ? (int)cdv.y : 0;
        v.w = (i0 + 3 < NN) ? (int)cdv.w : 0;
    }
    int s = v.x + v.y + v.z + v.w;
    int incl = s;
#pragma unroll
    for (int o = 1; o < 32; o <<= 1) {
        int y = __shfl_up_sync(0xFFFFFFFFu, incl, o);
        if (lane >= o) incl += y;
    }
    if (lane == 31) ws[wid] = incl;
    __syncthreads();
    if (wid == 0 && lane < 8) {
        int bv = ws[lane];
        int bi = bv;
#pragma unroll
        for (int o = 1; o < 8; o <<= 1) {
            int y = __shfl_up_sync(0xFFu, bi, o);
            if (lane >= o) bi += y;
        }
        ws[lane] = bi - bv;
        if (lane == 7) sh_total = bi;
    }
    __syncthreads();
    const int total = sh_total;
    const int excl_blk = ws[wid] + incl - s;

    if (wid == 0) {
        if (lane == 0) {
            g_aggr[b] = total;
            __threadfence();
            *(volatile int*)&g_flag[b] = 1;
        }
        int run = 0;
        int end = b;
        while (end > 0) {
            int j = end - 1 - lane;
            bool need = (j >= 0);
            int f = 0;
            do {
                if (need) f = *(volatile int*)&g_flag[j];
            } while (__ballot_sync(0xFFFFFFFFu, need && f == 0));
            __threadfence();
            unsigned m2 = __ballot_sync(0xFFFFFFFFu, need && f == 2);
            int val = 0;
            if (m2) {
                int k = __ffs(m2) - 1;
                if (need && lane < k) val = *(volatile int*)&g_aggr[j];
                else if (lane == k)   val = *(volatile int*)&g_incl[j];
                end = 0;
            } else {
                if (need) val = *(volatile int*)&g_aggr[j];
                end = (end >= 32) ? end - 32 : 0;
            }
#pragma unroll
            for (int o = 16; o > 0; o >>= 1)
                val += __shfl_down_sync(0xFFFFFFFFu, val, o);
            run += __shfl_sync(0xFFFFFFFFu, val, 0);
        }
        if (lane == 0) {
            sh_off = run;
            g_incl[b] = run + total;
            __threadfence();
            *(volatile int*)&g_flag[b] = 2;
        }
    }
    __syncthreads();
    const int base = sh_off + excl_blk;
    if (i0 < NN) {
        int st0 = base;
        int st1 = base + v.x;
        int st2 = st1 + v.y;
        int st3 = st2 + v.z;
        *(int4*)&g_start[i0] = make_int4(st0, st1, st2, st3);
        // packed {hsum_bits, cursor} — two int4 stores cover 4 nodes
        *(int4*)&g_hc[2 * i0] =
            make_int4(__float_as_int(hs.x), st0, __float_as_int(hs.y), st1);
        *(int4*)&g_hc[2 * i0 + 4] =
            make_int4(__float_as_int(hs.z), st2, __float_as_int(hs.w), st3);
    }
}

// ---------------------------------------------------------------------------
// K4: scatter, 2 edges/thread. hsum read + cursor atomic share one 8B sector.
// ---------------------------------------------------------------------------
__global__ __launch_bounds__(256) void k_scatter(const float* __restrict__ adj,
                                                 float* __restrict__ alpha_out) {
    int e = (blockIdx.x * blockDim.x + threadIdx.x) * 2;
    if (e >= EE) return;
    int4 sdp = *(const int4*)&g_sd[e];          // s0,d0,s1,d1
    float2 he = *(const float2*)&g_he[e];
    float2 ad = *(const float2*)&adj[e];
    float hs0 = __int_as_float(g_hc[2 * sdp.x]);
    float hs1 = __int_as_float(g_hc[2 * sdp.z]);
    float al0 = he.x / hs0;
    float al1 = he.y / hs1;
    if (alpha_out) *(float2*)&alpha_out[e] = make_float2(al0, al1);
    int p0 = atomicAdd(&g_hc[2 * sdp.x + 1], 1);
    g_pair[p0] = make_int2(sdp.y, __float_as_int(ad.x * al0));
    int p1 = atomicAdd(&g_hc[2 * sdp.z + 1], 1);
    g_pair[p1] = make_int2(sdp.w, __float_as_int(ad.y * al1));
}

// ---------------------------------------------------------------------------
// K5: per-node gather over fp16 h0. One warp per node, 8-deep MLP.
// ---------------------------------------------------------------------------
__global__ __launch_bounds__(256) void k_gather(float* __restrict__ out) {
    int warp = (blockIdx.x * blockDim.x + threadIdx.x) >> 5;
    int lane = threadIdx.x & 31;
    if (warp >= NN) return;
    const __half2* h0 = (const __half2*)g_h0h;
    int beg = g_start[warp];
    int cnt = (int)g_hd[warp].y;
    float a0 = 0.f, a1 = 0.f;
    for (int b = 0; b < cnt; b += 32) {
        int n = min(32, cnt - b);
        int2 pr = make_int2(0, 0);
        if (lane < n) pr = g_pair[beg + b + lane];
        int j = 0;
        for (; j + 8 <= n; j += 8) {
            int   d[8];
            float vv[8];
            __half2 xx[8];
#pragma unroll
            for (int q = 0; q < 8; q++) {
                d[q]  = __shfl_sync(0xFFFFFFFFu, pr.x, j + q);
                vv[q] = __int_as_float(__shfl_sync(0xFFFFFFFFu, pr.y, j + q));
            }
#pragma unroll
            for (int q = 0; q < 8; q++) xx[q] = __ldg(&h0[d[q] * 32 + lane]);
#pragma unroll
            for (int q = 0; q < 8; q++) {
                float2 f = __half22float2(xx[q]);
                a0 += vv[q] * f.x;
                a1 += vv[q] * f.y;
            }
        }
        for (; j < n; j++) {
            int dd = __shfl_sync(0xFFFFFFFFu, pr.x, j);
            float vv = __int_as_float(__shfl_sync(0xFFFFFFFFu, pr.y, j));
            float2 f = __half22float2(__ldg(&h0[dd * 32 + lane]));
            a0 += vv * f.x;
            a1 += vv * f.y;
        }
    }
    ((float2*)out)[warp * 32 + lane] = make_float2(a0, a1);
}

// ---------------------------------------------------------------------------
extern "C" void kernel_launch(void* const* d_in, const int* in_sizes, int n_in,
                              void* d_out, int out_size) {
    const float* x    = (const float*)d_in[0];
    const void*  ei   = d_in[1];
    const float* adj  = (const float*)d_in[2];
    const float* fc_w = (const float*)d_in[3];
    const float* a_w  = (const float*)d_in[4];
    const float* a_b  = (const float*)d_in[5];
    float* out = (float*)d_out;
    float* alpha_out = (out_size >= NN * HH + EE) ? (out + NN * HH) : nullptr;

    k_gemm<<<(NN + 127) / 128, 256>>>(x, fc_w, a_w);
    k_edge1<<<(EE / 2 + 255) / 256, 256>>>(ei, a_b);
    k_scan<<<NBLK, 256>>>();
    k_scatter<<<(EE / 2 + 255) / 256, 256>>>(adj, alpha_out);
    k_gather<<<(NN * 32 + 255) / 256, 256>>>(out);
}